// round 11
// baseline (speedup 1.0000x reference)
#include <cuda_runtime.h>
#include <cstdint>

#define BATCH   4
#define T       1024
#define HPIX    27
#define WPIX    48
#define HW      (HPIX * WPIX)   // 1296
#define NB      512
#define NK4     (NB / 4)        // 128 packed-u8 words per frame
#define LOOK    101
#define PAD     50
#define ODIM    128
#define WSTRIDE 104             // window row stride (16B aligned)
#define KSPLIT  4
#define NWIN    (BATCH * T * WSTRIDE)

// Scratch (device globals; no allocation in kernel_launch per harness rules)
__device__ uint32_t g_histP[BATCH * NK4 * T];     // packed u8 counts, [b][k4][t]
__device__ float    g_invn[BATCH * T];            // 1/||hist||
__device__ uint32_t g_winP[KSPLIT * NWIN];        // per-K-split integer partial windows

// ---------------------------------------------------------------------------
// Kernel 1: per-frame 512-bin color histogram -> packed u8 counts (transposed)
// + inverse L2 norm. (No zero-fill needed anymore: band writes every slab
// entry unconditionally.)
// ---------------------------------------------------------------------------
#define FPB 4
#define GPF (HW / 4)            // 324 quad-pixel groups per frame
#define NGRP (FPB * GPF)        // 1296
__global__ void __launch_bounds__(256) hist_kernel(const int* __restrict__ frames) {
    __shared__ int sh[FPB * NB];                      // 8 KB
    const int tid = threadIdx.x;
    const int f0  = blockIdx.x * FPB;                 // global frame base

    #pragma unroll
    for (int i = tid; i < FPB * NB; i += 256) sh[i] = 0;
    __syncthreads();

    const int4* base = (const int4*)(frames + (size_t)f0 * HW * 3);
    int  g = tid;
    int4 w0, w1, w2;
    if (g < NGRP) {
        w0 = base[3 * g + 0];
        w1 = base[3 * g + 1];
        w2 = base[3 * g + 2];
    }
    while (g < NGRP) {
        const int gn = g + 256;
        int4 n0, n1, n2;
        if (gn < NGRP) {                // prefetch next iteration
            n0 = base[3 * gn + 0];
            n1 = base[3 * gn + 1];
            n2 = base[3 * gn + 2];
        }
        int* h = sh + (g / GPF) * NB;
        atomicAdd(&h[((w0.x >> 5) << 6) | ((w0.y >> 5) << 3) | (w0.z >> 5)], 1);
        atomicAdd(&h[((w0.w >> 5) << 6) | ((w1.x >> 5) << 3) | (w1.y >> 5)], 1);
        atomicAdd(&h[((w1.z >> 5) << 6) | ((w1.w >> 5) << 3) | (w2.x >> 5)], 1);
        atomicAdd(&h[((w2.y >> 5) << 6) | ((w2.z >> 5) << 3) | (w2.w >> 5)], 1);
        g = gn; w0 = n0; w1 = n1; w2 = n2;
    }
    __syncthreads();

    // inverse norms: warp w handles frame w
    const int lane = tid & 31, w = tid >> 5;
    if (w < FPB) {
        float ss = 0.f;
        #pragma unroll
        for (int k = lane; k < NB; k += 32) {
            float c = (float)sh[w * NB + k];
            ss = fmaf(c, c, ss);
        }
        #pragma unroll
        for (int off = 16; off; off >>= 1) ss += __shfl_xor_sync(0xffffffffu, ss, off);
        if (lane == 0) g_invn[f0 + w] = rsqrtf(ss);   // ss >= 1 always
    }

    // pack 4 consecutive bins into u8x4, write k-major (transposed)
    const int b  = f0 >> 10;
    const int t0 = f0 & (T - 1);
    #pragma unroll
    for (int i = tid; i < NK4 * FPB; i += 256) {
        int f  = i & (FPB - 1);
        int k4 = i >> 2;
        int s  = f * NB + k4 * 4;
        uint32_t c0 = min(sh[s + 0], 255), c1 = min(sh[s + 1], 255);
        uint32_t c2 = min(sh[s + 2], 255), c3 = min(sh[s + 3], 255);
        g_histP[(b * NK4 + k4) * T + t0 + f] = c0 | (c1 << 8) | (c2 << 16) | (c3 << 24);
    }
}

// ---------------------------------------------------------------------------
// Kernel 2: banded correlation, W[t][l] = dot(h[t], h[t+l-50]) — computed
// DIRECTLY in (t,l) layout (R7's verified inner loop). Every dp4a is a
// needed band entry; plain uint4 stores to a per-K-split slab (no atomics,
// no zero-fill, no mirror scatter).
// Grid: 32 t-blocks x 4 batches x 4 K-splits = 512 blocks (~3.4/SM).
// Block: 32 t-rows x 104 l-cols, K = 32 words; micro-tile 4t x 4l;
// 208/256 threads compute, all 256 load.
// ---------------------------------------------------------------------------
#define BK4  16
#define KQ   (NK4 / KSPLIT)     // 32 words per K-split
#define NCH  (KQ / BK4)         // 2 chunks
#define TBLK 32
#define HSW  136                // strip: u in [tb-50, tb+85]

__global__ void __launch_bounds__(256) band_kernel() {
    const int bb = blockIdx.y;
    const int ks = blockIdx.z;
    const int tb = blockIdx.x * TBLK;

    __shared__ uint32_t Hs[2][BK4][HSW];   // 17.4 KB double-buffered strip

    const int tid = threadIdx.x;
    // compute mapping: 8 ty-groups x 26 tx-groups = 208 active
    const int  ty  = tid / 26;
    const int  tx  = tid - ty * 26;
    const bool act = (tid < 208);
    const int  j0  = ty * 4 + tx * 4;      // B window base (16B aligned)
    const int  ja  = ty * 4 + PAD;         // A base within strip (8B aligned)

    unsigned int acc[4][4];
    #pragma unroll
    for (int r = 0; r < 4; r++)
        #pragma unroll
        for (int c = 0; c < 4; c++) acc[r][c] = 0u;

    const uint32_t* hb = g_histP + (size_t)bb * NK4 * T + (size_t)ks * KQ * T;

    // strip loader (clamped to batch bounds -> zeros outside)
    auto load_chunk = [&](int ch, int buf) {
        #pragma unroll
        for (int i = tid; i < BK4 * HSW; i += 256) {
            int k = i / HSW, j = i - k * HSW;
            int u = tb - PAD + j;
            uint32_t v = 0u;
            if ((unsigned)u < (unsigned)T) v = hb[(size_t)(ch * BK4 + k) * T + u];
            Hs[buf][k][j] = v;
        }
    };

    load_chunk(0, 0);
    __syncthreads();

    #pragma unroll
    for (int ch = 0; ch < NCH; ch++) {
        const int cur = ch & 1;
        if (ch + 1 < NCH) load_chunk(ch + 1, cur ^ 1);
        if (act) {
            #pragma unroll
            for (int k = 0; k < BK4; k++) {
                uint2 a0 = *(const uint2*)&Hs[cur][k][ja];
                uint2 a1 = *(const uint2*)&Hs[cur][k][ja + 2];
                uint4 b0 = *(const uint4*)&Hs[cur][k][j0];
                uint4 b1 = *(const uint4*)&Hs[cur][k][j0 + 4];
                unsigned int ar[4] = {a0.x, a0.y, a1.x, a1.y};
                unsigned int bw[8] = {b0.x, b0.y, b0.z, b0.w, b1.x, b1.y, b1.z, b1.w};
                #pragma unroll
                for (int r = 0; r < 4; r++)
                    #pragma unroll
                    for (int c = 0; c < 4; c++)
                        acc[r][c] = __dp4a(ar[r], bw[r + c], acc[r][c]);
            }
        }
        __syncthreads();
    }

    // plain vector stores of integer partials to this K-split's slab
    if (act) {
        uint32_t* slab = g_winP + (size_t)ks * NWIN;
        #pragma unroll
        for (int r = 0; r < 4; r++) {
            int t = tb + ty * 4 + r;
            uint4 v = make_uint4(acc[r][0], acc[r][1], acc[r][2], acc[r][3]);
            *(uint4*)&slab[(size_t)(bb * T + t) * WSTRIDE + tx * 4] = v;
        }
    }
}

// ---------------------------------------------------------------------------
// Kernel 3: out = relu(win @ fc_w + fc_b), where win[t][l] =
// (sum of 4 slab partials) * invn[t] * invn[t+l-50], zeroed for l>=LOOK or
// u outside the batch. 512 blocks x 8 rows; 1 row x 4 channels per thread.
// ---------------------------------------------------------------------------
__global__ void __launch_bounds__(256) fc_kernel(const float* __restrict__ fc_w,
                                                 const float* __restrict__ fc_b,
                                                 float* __restrict__ out) {
    const int tid = threadIdx.x;
    const int g0  = blockIdx.x * 8;         // global frame base
    const int t0  = g0 & (T - 1);           // within-batch index
    const int bb  = g0 >> 10;

    __shared__ float sInv[112];             // invn[t0-50 .. t0+57], 0 outside batch
    __shared__ float wins[8][WSTRIDE];

    for (int i = tid; i < 108; i += 256) {
        int u = t0 - PAD + i;
        sInv[i] = ((unsigned)u < (unsigned)T) ? g_invn[bb * T + u] : 0.f;
    }
    __syncthreads();

    // stage window: sum 4 K-split slabs, normalize, boundary-zero
    for (int i = tid; i < 8 * (WSTRIDE / 4); i += 256) {
        int r = i / (WSTRIDE / 4), q = i - r * (WSTRIDE / 4);
        int l = q * 4;
        size_t off = (size_t)(g0 + r) * WSTRIDE + l;
        uint4 s0 = *(const uint4*)&g_winP[0 * NWIN + off];
        uint4 s1 = *(const uint4*)&g_winP[1 * NWIN + off];
        uint4 s2 = *(const uint4*)&g_winP[2 * NWIN + off];
        uint4 s3 = *(const uint4*)&g_winP[3 * NWIN + off];
        uint4 wi = make_uint4(s0.x + s1.x + s2.x + s3.x,
                              s0.y + s1.y + s2.y + s3.y,
                              s0.z + s1.z + s2.z + s3.z,
                              s0.w + s1.w + s2.w + s3.w);
        float ivt = sInv[r + PAD];
        wins[r][l + 0] = (l + 0 < LOOK) ? (float)wi.x * ivt * sInv[r + l + 0] : 0.f;
        wins[r][l + 1] = (l + 1 < LOOK) ? (float)wi.y * ivt * sInv[r + l + 1] : 0.f;
        wins[r][l + 2] = (l + 2 < LOOK) ? (float)wi.z * ivt * sInv[r + l + 2] : 0.f;
        wins[r][l + 3] = (l + 3 < LOOK) ? (float)wi.w * ivt * sInv[r + l + 3] : 0.f;
    }
    __syncthreads();

    const int tx = (tid & 31) * 4;          // output-channel base (0..124)
    const int r  = tid >> 5;                // row (0..7)

    float4 b4 = *(const float4*)(fc_b + tx);
    float a0o = b4.x, a1o = b4.y, a2o = b4.z, a3o = b4.w;

    for (int l = 0; l < LOOK; l++) {
        float4 wv = *(const float4*)(fc_w + l * ODIM + tx);
        float a = wins[r][l];
        a0o = fmaf(a, wv.x, a0o);
        a1o = fmaf(a, wv.y, a1o);
        a2o = fmaf(a, wv.z, a2o);
        a3o = fmaf(a, wv.w, a3o);
    }

    float4 o4;
    o4.x = fmaxf(a0o, 0.f);
    o4.y = fmaxf(a1o, 0.f);
    o4.z = fmaxf(a2o, 0.f);
    o4.w = fmaxf(a3o, 0.f);
    *(float4*)(out + (size_t)(g0 + r) * ODIM + tx) = o4;
}

// ---------------------------------------------------------------------------
extern "C" void kernel_launch(void* const* d_in, const int* in_sizes, int n_in,
                              void* d_out, int out_size) {
    const int*   frames = (const int*)d_in[0];
    const float* fc_w   = (const float*)d_in[1];
    const float* fc_b   = (const float*)d_in[2];
    float*       out    = (float*)d_out;

    hist_kernel<<<(BATCH * T) / FPB, 256>>>(frames);              // 1024 blocks
    band_kernel<<<dim3(T / TBLK, BATCH, KSPLIT), 256>>>();        // 512 blocks
    fc_kernel<<<(BATCH * T) / 8, 256>>>(fc_w, fc_b, out);         // 512 blocks
}